// round 1
// baseline (speedup 1.0000x reference)
#include <cuda_runtime.h>
#include <math.h>

#define DIM 512
#define HID 2048
#define NLAYERS 4
#define VOCAB 32000
#define BB 2
#define SS 2048
#define M_TOT (BB*SS)   // 4096

// ---------------- scratch (device globals; no allocation allowed) ----------------
__device__ float g_x [M_TOT*DIM];
__device__ float g_h [M_TOT*DIM];
__device__ float g_q [M_TOT*DIM];
__device__ float g_g [M_TOT*DIM];
__device__ float g_ao[M_TOT*DIM];
__device__ float g_f [M_TOT*DIM];
__device__ float g_a [M_TOT*HID];
__device__ float g_t [M_TOT*HID];
__device__ float g_nl[M_TOT];

__device__ __forceinline__ float silu_f(float v) {
    return v / (1.0f + __expf(-v));
}

// ---------------- embedding gather ----------------
__global__ void embed_kernel(const int* __restrict__ tok,
                             const float* __restrict__ emb,
                             float* __restrict__ X) {
    long idx = (long)blockIdx.x * 256 + threadIdx.x;   // over M_TOT*128 float4
    int row = (int)(idx >> 7);
    int c   = (int)(idx & 127);
    int t   = tok[row];
    reinterpret_cast<float4*>(X)[idx] =
        reinterpret_cast<const float4*>(emb + (long)t * DIM)[c];
}

// ---------------- RMSNorm (+ optional fused lambda dot -> log_sigmoid) ----------------
template<bool LAM>
__global__ void rmsnorm_kernel(const float* __restrict__ X,
                               const float* __restrict__ w,
                               const float* __restrict__ lam,
                               float* __restrict__ H,
                               float* __restrict__ NL) {
    __shared__ float sb[4];
    __shared__ float s_scale;
    const int row = blockIdx.x;
    const int t = threadIdx.x;               // 128 threads, 4 floats each
    float4 v = reinterpret_cast<const float4*>(X + (long)row * DIM)[t];
    float ss = v.x*v.x + v.y*v.y + v.z*v.z + v.w*v.w;
    #pragma unroll
    for (int o = 16; o > 0; o >>= 1) ss += __shfl_down_sync(0xffffffffu, ss, o);
    if ((t & 31) == 0) sb[t >> 5] = ss;
    __syncthreads();
    if (t == 0) {
        float tot = sb[0] + sb[1] + sb[2] + sb[3];
        s_scale = rsqrtf(tot / (float)DIM + 1e-6f);
    }
    __syncthreads();
    const float sc = s_scale;
    float4 wv = reinterpret_cast<const float4*>(w)[t];
    float4 h;
    h.x = v.x * sc * wv.x;
    h.y = v.y * sc * wv.y;
    h.z = v.z * sc * wv.z;
    h.w = v.w * sc * wv.w;
    reinterpret_cast<float4*>(H + (long)row * DIM)[t] = h;
    if (LAM) {
        float4 lv = reinterpret_cast<const float4*>(lam)[t];
        float d = h.x*lv.x + h.y*lv.y + h.z*lv.z + h.w*lv.w;
        #pragma unroll
        for (int o = 16; o > 0; o >>= 1) d += __shfl_down_sync(0xffffffffu, d, o);
        __syncthreads();                     // sb reuse
        if ((t & 31) == 0) sb[t >> 5] = d;
        __syncthreads();
        if (t == 0) {
            float dot = sb[0] + sb[1] + sb[2] + sb[3];
            // log_sigmoid, numerically stable
            float nl = (dot >= 0.0f) ? -log1pf(expf(-dot))
                                     : (dot - log1pf(expf(dot)));
            NL[row] = nl;
        }
    }
}

// ---------------- generic NT SGEMM: C = act(A) @ W^T (+ fused epilogues) -------------
// A: [M,K] row-major, W: [N,K] row-major. M,N multiples of 128; K multiple of 8.
// AACT: 0 none, 1 silu on A.
// EPI : 0 C=acc | 1 C+=acc | 2 C+=acc*E | 3 C=silu(acc)*E
template<int AACT, int EPI>
__global__ void __launch_bounds__(256, 2) gemm_nt(
    const float* __restrict__ A, const float* __restrict__ W,
    float* __restrict__ C, const float* __restrict__ E,
    int M, int N, int K)
{
    __shared__ float As[8][128];
    __shared__ float Ws[8][128];
    const int tid = threadIdx.x;
    const long bm = (long)blockIdx.y * 128;
    const long bn = (long)blockIdx.x * 128;
    const int lr = tid >> 1;            // 0..127
    const int lk = (tid & 1) << 2;      // 0 or 4
    const int tx = tid & 15;
    const int ty = tid >> 4;

    const float* Ap = A + (bm + lr) * (long)K + lk;
    const float* Wp = W + (bn + lr) * (long)K + lk;

    float acc[8][8];
    #pragma unroll
    for (int i = 0; i < 8; i++)
        #pragma unroll
        for (int j = 0; j < 8; j++) acc[i][j] = 0.0f;

    for (int k0 = 0; k0 < K; k0 += 8) {
        float4 av = *reinterpret_cast<const float4*>(Ap + k0);
        float4 wv = *reinterpret_cast<const float4*>(Wp + k0);
        if (AACT == 1) {
            av.x = silu_f(av.x); av.y = silu_f(av.y);
            av.z = silu_f(av.z); av.w = silu_f(av.w);
        }
        As[lk+0][lr] = av.x; As[lk+1][lr] = av.y;
        As[lk+2][lr] = av.z; As[lk+3][lr] = av.w;
        Ws[lk+0][lr] = wv.x; Ws[lk+1][lr] = wv.y;
        Ws[lk+2][lr] = wv.z; Ws[lk+3][lr] = wv.w;
        __syncthreads();
        #pragma unroll
        for (int kk = 0; kk < 8; kk++) {
            float4 a0 = *reinterpret_cast<const float4*>(&As[kk][ty*8]);
            float4 a1 = *reinterpret_cast<const float4*>(&As[kk][ty*8+4]);
            float4 b0 = *reinterpret_cast<const float4*>(&Ws[kk][tx*8]);
            float4 b1 = *reinterpret_cast<const float4*>(&Ws[kk][tx*8+4]);
            float a[8] = {a0.x,a0.y,a0.z,a0.w,a1.x,a1.y,a1.z,a1.w};
            float b[8] = {b0.x,b0.y,b0.z,b0.w,b1.x,b1.y,b1.z,b1.w};
            #pragma unroll
            for (int i = 0; i < 8; i++)
                #pragma unroll
                for (int j = 0; j < 8; j++)
                    acc[i][j] = fmaf(a[i], b[j], acc[i][j]);
        }
        __syncthreads();
    }

    #pragma unroll
    for (int i = 0; i < 8; i++) {
        long row  = bm + ty*8 + i;
        long base = row * (long)N + bn + tx*8;
        #pragma unroll
        for (int j = 0; j < 8; j++) {
            float v = acc[i][j];
            long idx = base + j;
            if      (EPI == 0) C[idx] = v;
            else if (EPI == 1) C[idx] += v;
            else if (EPI == 2) C[idx] += v * E[idx];
            else               C[idx] = silu_f(v) * E[idx];
        }
    }
}

// ---------------- decay attention: out[b,i,:] = sum_{j<=i} exp(nl[b,j]*(i-j)) q[b,j,:]
// grid (S/64, D/64, B), 256 threads, 4x4 microtile per thread
__global__ void __launch_bounds__(256) decay_attn(
    const float* __restrict__ Q, const float* __restrict__ NLv,
    float* __restrict__ O)
{
    const int it = blockIdx.x;
    const int dt = blockIdx.y;
    const int b  = blockIdx.z;
    const float* q  = Q + (long)b*SS*DIM + dt*64;
    const float* nl = NLv + (long)b*SS;
    __shared__ float qs[64][64];
    __shared__ float nls[64];
    __shared__ float sgs[64];
    const int tid = threadIdx.x;
    const int tx = tid & 15, ty = tid >> 4;
    float acc[4][4] = {};
    const int i0 = it*64 + ty*4;

    for (int jt = 0; jt <= it; jt++) {
        {
            int r = tid >> 4;            // 0..15
            int c = (tid & 15) * 4;      // 0..60
            #pragma unroll
            for (int rr = 0; rr < 64; rr += 16) {
                float4 v = *reinterpret_cast<const float4*>(
                    q + (long)(jt*64 + r + rr) * DIM + c);
                *reinterpret_cast<float4*>(&qs[r + rr][c]) = v;
            }
        }
        if (tid < 64) {
            float xv = nl[jt*64 + tid];
            nls[tid] = xv;
            sgs[tid] = expf(xv);         // exp(log_sigmoid) = sigmoid
        }
        __syncthreads();

        if (jt < it) {
            // strictly below diagonal: i-j >= 1 always, no mask needed
            #pragma unroll 2
            for (int j = 0; j < 64; j++) {
                float s = sgs[j];
                float w = expf(nls[j] * (float)(i0 - (jt*64 + j)));
                float4 qv = *reinterpret_cast<const float4*>(&qs[j][tx*4]);
                #pragma unroll
                for (int ii = 0; ii < 4; ii++) {
                    acc[ii][0] += w * qv.x;
                    acc[ii][1] += w * qv.y;
                    acc[ii][2] += w * qv.z;
                    acc[ii][3] += w * qv.w;
                    w *= s;              // exp(nl*(i+1-j)) = exp(nl*(i-j)) * sigmoid
                }
            }
        } else {
            // diagonal tile: needs causal mask
            for (int j = 0; j < 64; j++) {
                int jg = jt*64 + j;
                float4 qv = *reinterpret_cast<const float4*>(&qs[j][tx*4]);
                #pragma unroll
                for (int ii = 0; ii < 4; ii++) {
                    int d = i0 + ii - jg;
                    float w = (d >= 0) ? expf(nls[j] * (float)d) : 0.0f;
                    acc[ii][0] += w * qv.x;
                    acc[ii][1] += w * qv.y;
                    acc[ii][2] += w * qv.z;
                    acc[ii][3] += w * qv.w;
                }
            }
        }
        __syncthreads();
    }

    float* o = O + (long)b*SS*DIM + dt*64;
    #pragma unroll
    for (int ii = 0; ii < 4; ii++) {
        float4 v = {acc[ii][0], acc[ii][1], acc[ii][2], acc[ii][3]};
        *reinterpret_cast<float4*>(o + (long)(i0 + ii) * DIM + tx*4) = v;
    }
}

// ---------------- orchestration ----------------
extern "C" void kernel_launch(void* const* d_in, const int* in_sizes, int n_in,
                              void* d_out, int out_size) {
    const int*   tokens       = (const int*)  d_in[0];
    const float* emb          = (const float*)d_in[1];
    const float* decay_norm_w = (const float*)d_in[2];
    const float* lambda_w     = (const float*)d_in[3];
    const float* quantity_w   = (const float*)d_in[4];
    const float* gate_w       = (const float*)d_in[5];
    const float* output_w     = (const float*)d_in[6];
    const float* ffn_norm_w   = (const float*)d_in[7];
    const float* w_h          = (const float*)d_in[8];
    const float* w_g          = (const float*)d_in[9];
    const float* w_o          = (const float*)d_in[10];
    const float* out_norm_w   = (const float*)d_in[11];
    float* out = (float*)d_out;

    float *x, *h, *q, *g, *ao, *f, *a, *t, *nl;
    cudaGetSymbolAddress((void**)&x,  g_x);
    cudaGetSymbolAddress((void**)&h,  g_h);
    cudaGetSymbolAddress((void**)&q,  g_q);
    cudaGetSymbolAddress((void**)&g,  g_g);
    cudaGetSymbolAddress((void**)&ao, g_ao);
    cudaGetSymbolAddress((void**)&f,  g_f);
    cudaGetSymbolAddress((void**)&a,  g_a);
    cudaGetSymbolAddress((void**)&t,  g_t);
    cudaGetSymbolAddress((void**)&nl, g_nl);

    embed_kernel<<<M_TOT * (DIM/4) / 256, 256>>>(tokens, emb, x);

    dim3 g512 (DIM/128,   M_TOT/128);   // (4,  32)
    dim3 g2048(HID/128,   M_TOT/128);   // (16, 32)
    dim3 gV   (VOCAB/128, M_TOT/128);   // (250,32)
    dim3 gattn(SS/64, DIM/64, BB);      // (32, 8, 2)

    for (int l = 0; l < NLAYERS; l++) {
        // h = rmsnorm(x, decay_norm_w);  nl = log_sigmoid(h . lambda)
        rmsnorm_kernel<true><<<M_TOT, 128>>>(x, decay_norm_w + l*DIM,
                                             lambda_w + l*DIM, h, nl);
        // q = h @ Wq^T ; g = h @ Wg^T
        gemm_nt<0,0><<<g512, 256>>>(h, quantity_w + (long)l*DIM*DIM, q, nullptr,
                                    M_TOT, DIM, DIM);
        gemm_nt<0,0><<<g512, 256>>>(h, gate_w + (long)l*DIM*DIM, g, nullptr,
                                    M_TOT, DIM, DIM);
        // ao = decay @ q
        decay_attn<<<gattn, 256>>>(q, nl, ao);
        // x += (silu(ao) @ Wout^T) * g
        gemm_nt<1,2><<<g512, 256>>>(ao, output_w + (long)l*DIM*DIM, x, g,
                                    M_TOT, DIM, DIM);
        // f = rmsnorm(x, ffn_norm_w)
        rmsnorm_kernel<false><<<M_TOT, 128>>>(x, ffn_norm_w + l*DIM,
                                              nullptr, f, nullptr);
        // a = f @ w_h^T ; t = silu(f @ w_g^T) * a ; x += t @ w_o^T
        gemm_nt<0,0><<<g2048, 256>>>(f, w_h + (long)l*HID*DIM, a, nullptr,
                                     M_TOT, HID, DIM);
        gemm_nt<0,3><<<g2048, 256>>>(f, w_g + (long)l*HID*DIM, t, a,
                                     M_TOT, HID, DIM);
        gemm_nt<0,1><<<g512, 256>>>(t, w_o + (long)l*DIM*HID, x, nullptr,
                                    M_TOT, DIM, HID);
    }

    // logits = rmsnorm(x, out_norm_w) @ emb^T
    rmsnorm_kernel<false><<<M_TOT, 128>>>(x, out_norm_w, nullptr, h, nullptr);
    gemm_nt<0,0><<<gV, 256>>>(h, emb, out, nullptr, M_TOT, VOCAB, DIM);
}

// round 2
// speedup vs baseline: 1.5476x; 1.5476x over previous
#include <cuda_runtime.h>
#include <math.h>

#define DIM 512
#define HID 2048
#define NLAYERS 4
#define VOCAB 32000
#define BB 2
#define SS 2048
#define M_TOT (BB*SS)   // 4096

// ---------------- scratch (device globals; no allocation allowed) ----------------
__device__ float g_x [M_TOT*DIM];
__device__ float g_h [M_TOT*DIM];
__device__ float g_q [M_TOT*DIM];
__device__ float g_g [M_TOT*DIM];
__device__ float g_ao[M_TOT*DIM];
__device__ float g_f [M_TOT*DIM];
__device__ float g_a [M_TOT*HID];
__device__ float g_t [M_TOT*HID];
__device__ float g_nl[M_TOT];
__device__ float g_nlmax[M_TOT/64];

__device__ __forceinline__ float silu_f(float v) {
    return v / (1.0f + __expf(-v));
}

__device__ __forceinline__ unsigned f2tf32(float x) {
    unsigned r;
    asm("cvt.rna.tf32.f32 %0, %1;" : "=r"(r) : "f"(x));
    return r;
}

__device__ __forceinline__ void mma_tf32(float* c, const unsigned* a, const unsigned* b) {
    asm volatile(
        "mma.sync.aligned.m16n8k8.row.col.f32.tf32.tf32.f32 "
        "{%0,%1,%2,%3}, {%4,%5,%6,%7}, {%8,%9}, {%0,%1,%2,%3};"
        : "+f"(c[0]), "+f"(c[1]), "+f"(c[2]), "+f"(c[3])
        : "r"(a[0]), "r"(a[1]), "r"(a[2]), "r"(a[3]), "r"(b[0]), "r"(b[1]));
}

// ---------------- embedding gather ----------------
__global__ void embed_kernel(const int* __restrict__ tok,
                             const float* __restrict__ emb,
                             float* __restrict__ X) {
    long idx = (long)blockIdx.x * 256 + threadIdx.x;
    int row = (int)(idx >> 7);
    int c   = (int)(idx & 127);
    int t   = tok[row];
    reinterpret_cast<float4*>(X)[idx] =
        reinterpret_cast<const float4*>(emb + (long)t * DIM)[c];
}

// ---------------- RMSNorm (+ optional fused lambda dot -> log_sigmoid) ----------------
template<bool LAM>
__global__ void rmsnorm_kernel(const float* __restrict__ X,
                               const float* __restrict__ w,
                               const float* __restrict__ lam,
                               float* __restrict__ H,
                               float* __restrict__ NL) {
    __shared__ float sb[4];
    __shared__ float s_scale;
    const int row = blockIdx.x;
    const int t = threadIdx.x;               // 128 threads, 4 floats each
    float4 v = reinterpret_cast<const float4*>(X + (long)row * DIM)[t];
    float ss = v.x*v.x + v.y*v.y + v.z*v.z + v.w*v.w;
    #pragma unroll
    for (int o = 16; o > 0; o >>= 1) ss += __shfl_down_sync(0xffffffffu, ss, o);
    if ((t & 31) == 0) sb[t >> 5] = ss;
    __syncthreads();
    if (t == 0) {
        float tot = sb[0] + sb[1] + sb[2] + sb[3];
        s_scale = rsqrtf(tot / (float)DIM + 1e-6f);
    }
    __syncthreads();
    const float sc = s_scale;
    float4 wv = reinterpret_cast<const float4*>(w)[t];
    float4 h;
    h.x = v.x * sc * wv.x;
    h.y = v.y * sc * wv.y;
    h.z = v.z * sc * wv.z;
    h.w = v.w * sc * wv.w;
    reinterpret_cast<float4*>(H + (long)row * DIM)[t] = h;
    if (LAM) {
        float4 lv = reinterpret_cast<const float4*>(lam)[t];
        float d = h.x*lv.x + h.y*lv.y + h.z*lv.z + h.w*lv.w;
        #pragma unroll
        for (int o = 16; o > 0; o >>= 1) d += __shfl_down_sync(0xffffffffu, d, o);
        __syncthreads();
        if ((t & 31) == 0) sb[t >> 5] = d;
        __syncthreads();
        if (t == 0) {
            float dot = sb[0] + sb[1] + sb[2] + sb[3];
            float nl = (dot >= 0.0f) ? -log1pf(expf(-dot))
                                     : (dot - log1pf(expf(dot)));
            NL[row] = nl;
        }
    }
}

// per-64-row-tile max of nl (for decay band pruning)
__global__ void nlmax_kernel(const float* __restrict__ NL, float* __restrict__ NM) {
    int base = blockIdx.x * 64;
    int lid = threadIdx.x;  // 32
    float v = fmaxf(NL[base + lid], NL[base + 32 + lid]);
    #pragma unroll
    for (int o = 16; o > 0; o >>= 1) v = fmaxf(v, __shfl_xor_sync(0xffffffffu, v, o));
    if (lid == 0) NM[blockIdx.x] = v;
}

// ---------------- staging helper: fp32 -> permuted tf32 (hi / hi+lo) smem ----------
// slot(k) = (k%4)*4 + k/4  so thread tc's 4 k-values {tc, tc+4, tc+8, tc+12} are contiguous.
template<bool SPLIT, int AACT>
__device__ __forceinline__ void stage_row(float* S, int row, int i4, float4 v) {
    float e[4] = {v.x, v.y, v.z, v.w};
    #pragma unroll
    for (int j = 0; j < 4; j++) {
        float x = e[j];
        if (AACT == 1) x = silu_f(x);
        int slot = j * 4 + i4;
        if (SPLIT) {
            unsigned hb = f2tf32(x);
            float hf = __uint_as_float(hb);
            float lf = __uint_as_float(f2tf32(x - hf));
            *reinterpret_cast<float2*>(&S[row * 36 + slot * 2]) = make_float2(hf, lf);
        } else {
            S[row * 16 + slot] = __uint_as_float(f2tf32(x));
        }
    }
}

// ---------------- tensor-core NT GEMM: C = act(A) @ W^T (+ fused epilogues) ---------
// A: [M,K] rm, W: [N,K] rm. Tile 128x128, k-chunk 16, 8 warps, warptile 64x32.
// SPLIT=true: 3xTF32 error-compensated (~fp32 accuracy). SPLIT=false: plain TF32.
// AACT: 0 none, 1 silu(A). EPI: 0 C=acc | 1 C+=acc | 2 C+=acc*E | 3 C=silu(acc)*E
template<bool SPLIT, int AACT, int EPI>
__global__ void __launch_bounds__(256) gemm_tc(
    const float* __restrict__ A, const float* __restrict__ W,
    float* __restrict__ C, const float* __restrict__ E,
    int M, int N, int K)
{
    constexpr int RS = SPLIT ? 36 : 16;   // smem row stride (floats)
    __shared__ float As[128 * RS];
    __shared__ float Bs[128 * RS];

    const int tid  = threadIdx.x;
    const int lane = tid & 31;
    const int gr   = lane >> 2;     // group row 0..7
    const int tc   = lane & 3;      // thread-in-group 0..3
    const int warp = tid >> 5;
    const int wm   = warp >> 2;     // 0..1
    const int wn   = warp & 3;      // 0..3
    const long bm = (long)blockIdx.y * 128;
    const long bn = (long)blockIdx.x * 128;

    const int r0 = tid >> 2;        // staging row (0..63), second batch +64
    const int i4 = tid & 3;

    const float* Ag = A + (bm + r0) * (long)K + i4 * 4;
    const float* Bg = W + (bn + r0) * (long)K + i4 * 4;
    const long halfA = 64 * (long)K;

    float acc[4][4][4];
    #pragma unroll
    for (int mi = 0; mi < 4; mi++)
        #pragma unroll
        for (int ni = 0; ni < 4; ni++)
            #pragma unroll
            for (int r = 0; r < 4; r++) acc[mi][ni][r] = 0.0f;

    float4 ra0 = *reinterpret_cast<const float4*>(Ag);
    float4 ra1 = *reinterpret_cast<const float4*>(Ag + halfA);
    float4 rb0 = *reinterpret_cast<const float4*>(Bg);
    float4 rb1 = *reinterpret_cast<const float4*>(Bg + halfA);

    for (int k0 = 0; k0 < K; k0 += 16) {
        stage_row<SPLIT, AACT>(As, r0,      i4, ra0);
        stage_row<SPLIT, AACT>(As, r0 + 64, i4, ra1);
        stage_row<SPLIT, 0   >(Bs, r0,      i4, rb0);
        stage_row<SPLIT, 0   >(Bs, r0 + 64, i4, rb1);
        __syncthreads();

        if (k0 + 16 < K) {
            ra0 = *reinterpret_cast<const float4*>(Ag + k0 + 16);
            ra1 = *reinterpret_cast<const float4*>(Ag + halfA + k0 + 16);
            rb0 = *reinterpret_cast<const float4*>(Bg + k0 + 16);
            rb1 = *reinterpret_cast<const float4*>(Bg + halfA + k0 + 16);
        }

        if (SPLIT) {
            #pragma unroll
            for (int s = 0; s < 2; s++) {
                unsigned ahi[4][4], alo[4][4];
                #pragma unroll
                for (int mi = 0; mi < 4; mi++) {
                    int r = wm * 64 + mi * 16 + gr;
                    float4 p  = *reinterpret_cast<const float4*>(&As[r * 36 + (4*tc + 2*s) * 2]);
                    float4 p2 = *reinterpret_cast<const float4*>(&As[(r + 8) * 36 + (4*tc + 2*s) * 2]);
                    ahi[mi][0] = __float_as_uint(p.x);  alo[mi][0] = __float_as_uint(p.y);
                    ahi[mi][1] = __float_as_uint(p2.x); alo[mi][1] = __float_as_uint(p2.y);
                    ahi[mi][2] = __float_as_uint(p.z);  alo[mi][2] = __float_as_uint(p.w);
                    ahi[mi][3] = __float_as_uint(p2.z); alo[mi][3] = __float_as_uint(p2.w);
                }
                unsigned bhi[4][2], blo[4][2];
                #pragma unroll
                for (int ni = 0; ni < 4; ni++) {
                    float4 pb = *reinterpret_cast<const float4*>(
                        &Bs[(wn * 32 + ni * 8 + gr) * 36 + (4*tc + 2*s) * 2]);
                    bhi[ni][0] = __float_as_uint(pb.x); blo[ni][0] = __float_as_uint(pb.y);
                    bhi[ni][1] = __float_as_uint(pb.z); blo[ni][1] = __float_as_uint(pb.w);
                }
                #pragma unroll
                for (int mi = 0; mi < 4; mi++)
                    #pragma unroll
                    for (int ni = 0; ni < 4; ni++) {
                        mma_tf32(acc[mi][ni], ahi[mi], bhi[ni]);
                        mma_tf32(acc[mi][ni], alo[mi], bhi[ni]);
                        mma_tf32(acc[mi][ni], ahi[mi], blo[ni]);
                    }
            }
        } else {
            unsigned af[4][2][4];
            #pragma unroll
            for (int mi = 0; mi < 4; mi++) {
                int r = wm * 64 + mi * 16 + gr;
                float4 p  = *reinterpret_cast<const float4*>(&As[r * 16 + 4 * tc]);
                float4 p2 = *reinterpret_cast<const float4*>(&As[(r + 8) * 16 + 4 * tc]);
                af[mi][0][0] = __float_as_uint(p.x);  af[mi][0][1] = __float_as_uint(p2.x);
                af[mi][0][2] = __float_as_uint(p.y);  af[mi][0][3] = __float_as_uint(p2.y);
                af[mi][1][0] = __float_as_uint(p.z);  af[mi][1][1] = __float_as_uint(p2.z);
                af[mi][1][2] = __float_as_uint(p.w);  af[mi][1][3] = __float_as_uint(p2.w);
            }
            unsigned bf[4][2][2];
            #pragma unroll
            for (int ni = 0; ni < 4; ni++) {
                float4 pb = *reinterpret_cast<const float4*>(
                    &Bs[(wn * 32 + ni * 8 + gr) * 16 + 4 * tc]);
                bf[ni][0][0] = __float_as_uint(pb.x); bf[ni][0][1] = __float_as_uint(pb.y);
                bf[ni][1][0] = __float_as_uint(pb.z); bf[ni][1][1] = __float_as_uint(pb.w);
            }
            #pragma unroll
            for (int s = 0; s < 2; s++)
                #pragma unroll
                for (int mi = 0; mi < 4; mi++)
                    #pragma unroll
                    for (int ni = 0; ni < 4; ni++)
                        mma_tf32(acc[mi][ni], af[mi][s], bf[ni][s]);
        }
        __syncthreads();
    }

    // epilogue
    #pragma unroll
    for (int mi = 0; mi < 4; mi++) {
        #pragma unroll
        for (int ni = 0; ni < 4; ni++) {
            long row = bm + wm * 64 + mi * 16 + gr;
            long col = bn + wn * 32 + ni * 8 + tc * 2;
            float* a = acc[mi][ni];
            long i0 = row * (long)N + col;
            long i1 = (row + 8) * (long)N + col;
            float2 o0, o1;
            if (EPI == 0) {
                o0 = make_float2(a[0], a[1]);
                o1 = make_float2(a[2], a[3]);
            } else if (EPI == 1) {
                float2 c0 = *reinterpret_cast<float2*>(&C[i0]);
                float2 c1 = *reinterpret_cast<float2*>(&C[i1]);
                o0 = make_float2(c0.x + a[0], c0.y + a[1]);
                o1 = make_float2(c1.x + a[2], c1.y + a[3]);
            } else if (EPI == 2) {
                float2 c0 = *reinterpret_cast<float2*>(&C[i0]);
                float2 c1 = *reinterpret_cast<float2*>(&C[i1]);
                float2 e0 = *reinterpret_cast<const float2*>(&E[i0]);
                float2 e1 = *reinterpret_cast<const float2*>(&E[i1]);
                o0 = make_float2(c0.x + a[0]*e0.x, c0.y + a[1]*e0.y);
                o1 = make_float2(c1.x + a[2]*e1.x, c1.y + a[3]*e1.y);
            } else {
                float2 e0 = *reinterpret_cast<const float2*>(&E[i0]);
                float2 e1 = *reinterpret_cast<const float2*>(&E[i1]);
                o0 = make_float2(silu_f(a[0])*e0.x, silu_f(a[1])*e0.y);
                o1 = make_float2(silu_f(a[2])*e1.x, silu_f(a[3])*e1.y);
            }
            *reinterpret_cast<float2*>(&C[i0]) = o0;
            *reinterpret_cast<float2*>(&C[i1]) = o1;
        }
    }
}

// ---------------- decay attention with band pruning -------------------------------
// out[b,i,:] = sum_{j<=i} exp(nl[b,j]*(i-j)) q[b,j,:]
__global__ void __launch_bounds__(256) decay_attn(
    const float* __restrict__ Q, const float* __restrict__ NLv,
    const float* __restrict__ NM, float* __restrict__ O)
{
    const int it = blockIdx.x;
    const int dt = blockIdx.y;
    const int b  = blockIdx.z;
    const float* q  = Q + (long)b*SS*DIM + dt*64;
    const float* nl = NLv + (long)b*SS;
    const float* nlmax = NM + b*(SS/64);
    __shared__ float qs[64][64];
    __shared__ float nls[64];
    __shared__ float sgs[64];
    const int tid = threadIdx.x;
    const int tx = tid & 15, ty = tid >> 4;
    float acc[4][4] = {};
    const int i0 = it*64 + ty*4;

    for (int jt = 0; jt <= it; jt++) {
        if (jt < it) {
            // all weights in this tile <= exp(nlmax * dmin); skip if < e^-40
            float dmin = (float)(it*64 - (jt*64 + 63));
            if (nlmax[jt] * dmin < -40.0f) continue;
        }
        {
            int r = tid >> 4;
            int c = (tid & 15) * 4;
            #pragma unroll
            for (int rr = 0; rr < 64; rr += 16) {
                float4 v = *reinterpret_cast<const float4*>(
                    q + (long)(jt*64 + r + rr) * DIM + c);
                *reinterpret_cast<float4*>(&qs[r + rr][c]) = v;
            }
        }
        if (tid < 64) {
            float xv = nl[jt*64 + tid];
            nls[tid] = xv;
            sgs[tid] = expf(xv);
        }
        __syncthreads();

        if (jt < it) {
            #pragma unroll 2
            for (int j = 0; j < 64; j++) {
                float s = sgs[j];
                float w = expf(nls[j] * (float)(i0 - (jt*64 + j)));
                float4 qv = *reinterpret_cast<const float4*>(&qs[j][tx*4]);
                #pragma unroll
                for (int ii = 0; ii < 4; ii++) {
                    acc[ii][0] += w * qv.x;
                    acc[ii][1] += w * qv.y;
                    acc[ii][2] += w * qv.z;
                    acc[ii][3] += w * qv.w;
                    w *= s;
                }
            }
        } else {
            for (int j = 0; j < 64; j++) {
                int jg = jt*64 + j;
                float4 qv = *reinterpret_cast<const float4*>(&qs[j][tx*4]);
                #pragma unroll
                for (int ii = 0; ii < 4; ii++) {
                    int d = i0 + ii - jg;
                    float w = (d >= 0) ? expf(nls[j] * (float)d) : 0.0f;
                    acc[ii][0] += w * qv.x;
                    acc[ii][1] += w * qv.y;
                    acc[ii][2] += w * qv.z;
                    acc[ii][3] += w * qv.w;
                }
            }
        }
        __syncthreads();
    }

    float* o = O + (long)b*SS*DIM + dt*64;
    #pragma unroll
    for (int ii = 0; ii < 4; ii++) {
        float4 v = {acc[ii][0], acc[ii][1], acc[ii][2], acc[ii][3]};
        *reinterpret_cast<float4*>(o + (long)(i0 + ii) * DIM + tx*4) = v;
    }
}

// ---------------- orchestration ----------------
extern "C" void kernel_launch(void* const* d_in, const int* in_sizes, int n_in,
                              void* d_out, int out_size) {
    const int*   tokens       = (const int*)  d_in[0];
    const float* emb          = (const float*)d_in[1];
    const float* decay_norm_w = (const float*)d_in[2];
    const float* lambda_w     = (const float*)d_in[3];
    const float* quantity_w   = (const float*)d_in[4];
    const float* gate_w       = (const float*)d_in[5];
    const float* output_w     = (const float*)d_in[6];
    const float* ffn_norm_w   = (const float*)d_in[7];
    const float* w_h          = (const float*)d_in[8];
    const float* w_g          = (const float*)d_in[9];
    const float* w_o          = (const float*)d_in[10];
    const float* out_norm_w   = (const float*)d_in[11];
    float* out = (float*)d_out;

    float *x, *h, *q, *g, *ao, *f, *a, *t, *nl, *nm;
    cudaGetSymbolAddress((void**)&x,  g_x);
    cudaGetSymbolAddress((void**)&h,  g_h);
    cudaGetSymbolAddress((void**)&q,  g_q);
    cudaGetSymbolAddress((void**)&g,  g_g);
    cudaGetSymbolAddress((void**)&ao, g_ao);
    cudaGetSymbolAddress((void**)&f,  g_f);
    cudaGetSymbolAddress((void**)&a,  g_a);
    cudaGetSymbolAddress((void**)&t,  g_t);
    cudaGetSymbolAddress((void**)&nl, g_nl);
    cudaGetSymbolAddress((void**)&nm, g_nlmax);

    embed_kernel<<<M_TOT * (DIM/4) / 256, 256>>>(tokens, emb, x);

    dim3 g512 (DIM/128,   M_TOT/128);   // (4,  32)
    dim3 g2048(HID/128,   M_TOT/128);   // (16, 32)
    dim3 gV   (VOCAB/128, M_TOT/128);   // (250,32)
    dim3 gattn(SS/64, DIM/64, BB);      // (32, 8, 2)

    for (int l = 0; l < NLAYERS; l++) {
        rmsnorm_kernel<true><<<M_TOT, 128>>>(x, decay_norm_w + l*DIM,
                                             lambda_w + l*DIM, h, nl);
        nlmax_kernel<<<M_TOT/64, 32>>>(nl, nm);
        gemm_tc<true,0,0><<<g512, 256>>>(h, quantity_w + (long)l*DIM*DIM, q, nullptr,
                                         M_TOT, DIM, DIM);
        gemm_tc<true,0,0><<<g512, 256>>>(h, gate_w + (long)l*DIM*DIM, g, nullptr,
                                         M_TOT, DIM, DIM);
        decay_attn<<<gattn, 256>>>(q, nl, nm, ao);
        gemm_tc<true,1,2><<<g512, 256>>>(ao, output_w + (long)l*DIM*DIM, x, g,
                                         M_TOT, DIM, DIM);
        rmsnorm_kernel<false><<<M_TOT, 128>>>(x, ffn_norm_w + l*DIM,
                                              nullptr, f, nullptr);
        gemm_tc<true,0,0><<<g2048, 256>>>(f, w_h + (long)l*HID*DIM, a, nullptr,
                                          M_TOT, HID, DIM);
        gemm_tc<true,0,3><<<g2048, 256>>>(f, w_g + (long)l*HID*DIM, t, a,
                                          M_TOT, HID, DIM);
        gemm_tc<true,0,1><<<g512, 256>>>(t, w_o + (long)l*DIM*HID, x, nullptr,
                                         M_TOT, DIM, HID);
    }

    rmsnorm_kernel<false><<<M_TOT, 128>>>(x, out_norm_w, nullptr, h, nullptr);
    gemm_tc<false,0,0><<<gV, 256>>>(h, emb, out, nullptr, M_TOT, VOCAB, DIM);
}

// round 3
// speedup vs baseline: 2.7376x; 1.7689x over previous
#include <cuda_runtime.h>
#include <cuda_fp16.h>
#include <math.h>

#define DIM 512
#define HID 2048
#define NLAYERS 4
#define VOCAB 32000
#define BB 2
#define SS 2048
#define M_TOT (BB*SS)   // 4096

// ---------------- scratch (device globals; no allocation allowed) ----------------
__device__ float g_x [M_TOT*DIM];
__device__ float g_h [M_TOT*DIM];
__device__ float g_q [M_TOT*DIM];
__device__ float g_g [M_TOT*DIM];
__device__ float g_ao[M_TOT*DIM];
__device__ float g_f [M_TOT*DIM];
__device__ float g_a [M_TOT*HID];
__device__ float g_t [M_TOT*HID];
__device__ float g_nl[M_TOT];
__device__ float g_nlmax[M_TOT/64];

__device__ __forceinline__ float silu_f(float v) {
    return v / (1.0f + __expf(-v));
}

__device__ __forceinline__ unsigned hpack(__half a, __half b) {
    __half2 t = __halves2half2(a, b);
    return *reinterpret_cast<unsigned*>(&t);
}

// fp16 tensor-core mma, fp32 accumulate
__device__ __forceinline__ void mma_f16(float* c, const unsigned* a, const unsigned* b) {
    asm volatile(
        "mma.sync.aligned.m16n8k16.row.col.f32.f16.f16.f32 "
        "{%0,%1,%2,%3}, {%4,%5,%6,%7}, {%8,%9}, {%0,%1,%2,%3};"
        : "+f"(c[0]), "+f"(c[1]), "+f"(c[2]), "+f"(c[3])
        : "r"(a[0]), "r"(a[1]), "r"(a[2]), "r"(a[3]), "r"(b[0]), "r"(b[1]));
}

// ---------------- embedding gather ----------------
__global__ void embed_kernel(const int* __restrict__ tok,
                             const float* __restrict__ emb,
                             float* __restrict__ X) {
    long idx = (long)blockIdx.x * 256 + threadIdx.x;
    int row = (int)(idx >> 7);
    int c   = (int)(idx & 127);
    int t   = tok[row];
    reinterpret_cast<float4*>(X)[idx] =
        reinterpret_cast<const float4*>(emb + (long)t * DIM)[c];
}

// ---------------- RMSNorm (+ optional fused lambda dot -> log_sigmoid) ----------------
template<bool LAM>
__global__ void rmsnorm_kernel(const float* __restrict__ X,
                               const float* __restrict__ w,
                               const float* __restrict__ lam,
                               float* __restrict__ H,
                               float* __restrict__ NL) {
    __shared__ float sb[4];
    __shared__ float s_scale;
    const int row = blockIdx.x;
    const int t = threadIdx.x;               // 128 threads, 4 floats each
    float4 v = reinterpret_cast<const float4*>(X + (long)row * DIM)[t];
    float ss = v.x*v.x + v.y*v.y + v.z*v.z + v.w*v.w;
    #pragma unroll
    for (int o = 16; o > 0; o >>= 1) ss += __shfl_down_sync(0xffffffffu, ss, o);
    if ((t & 31) == 0) sb[t >> 5] = ss;
    __syncthreads();
    if (t == 0) {
        float tot = sb[0] + sb[1] + sb[2] + sb[3];
        s_scale = rsqrtf(tot / (float)DIM + 1e-6f);
    }
    __syncthreads();
    const float sc = s_scale;
    float4 wv = reinterpret_cast<const float4*>(w)[t];
    float4 h;
    h.x = v.x * sc * wv.x;
    h.y = v.y * sc * wv.y;
    h.z = v.z * sc * wv.z;
    h.w = v.w * sc * wv.w;
    reinterpret_cast<float4*>(H + (long)row * DIM)[t] = h;
    if (LAM) {
        float4 lv = reinterpret_cast<const float4*>(lam)[t];
        float d = h.x*lv.x + h.y*lv.y + h.z*lv.z + h.w*lv.w;
        #pragma unroll
        for (int o = 16; o > 0; o >>= 1) d += __shfl_down_sync(0xffffffffu, d, o);
        __syncthreads();
        if ((t & 31) == 0) sb[t >> 5] = d;
        __syncthreads();
        if (t == 0) {
            float dot = sb[0] + sb[1] + sb[2] + sb[3];
            float nl = (dot >= 0.0f) ? -log1pf(expf(-dot))
                                     : (dot - log1pf(expf(dot)));
            NL[row] = nl;
        }
    }
}

// per-64-row-tile max of nl (for decay band pruning)
__global__ void nlmax_kernel(const float* __restrict__ NL, float* __restrict__ NM) {
    int base = blockIdx.x * 64;
    int lid = threadIdx.x;  // 32
    float v = fmaxf(NL[base + lid], NL[base + 32 + lid]);
    #pragma unroll
    for (int o = 16; o > 0; o >>= 1) v = fmaxf(v, __shfl_xor_sync(0xffffffffu, v, o));
    if (lid == 0) NM[blockIdx.x] = v;
}

// ---------------- staging: fp32 -> fp16 (hi / hi+lo) permuted smem ----------------
// k-pair p (k=2p,2p+1), p=0..7 per 16-k chunk.
// SPLIT layout (16 u32/row): chunk c=p%4 at u32 offset c*4; [H,L] at +0 (p<4) or +2 (p>=4).
//   -> reader (thread tc) does one uint4 at tc*4: {H[tc],L[tc],H[tc+4],L[tc+4]}
// non-SPLIT layout (8 u32/row): H[p] at (p%4)*2 + (p>=4)
//   -> reader does one uint2 at tc*2: {H[tc], H[tc+4]}
template<bool SPLIT, int AACT>
__device__ __forceinline__ void stage_row(unsigned* S, int row, int i4, float4 v) {
    float x0 = v.x, x1 = v.y, x2 = v.z, x3 = v.w;
    if (AACT == 1) {
        x0 = silu_f(x0); x1 = silu_f(x1);
        x2 = silu_f(x2); x3 = silu_f(x3);
    }
    __half h0 = __float2half_rn(x0), h1 = __float2half_rn(x1);
    __half h2 = __float2half_rn(x2), h3 = __float2half_rn(x3);
    unsigned H0 = hpack(h0, h1);
    unsigned H1 = hpack(h2, h3);
    int p0 = 2 * i4, p1 = 2 * i4 + 1;
    if (SPLIT) {
        unsigned L0 = hpack(__float2half_rn(x0 - __half2float(h0)),
                            __float2half_rn(x1 - __half2float(h1)));
        unsigned L1 = hpack(__float2half_rn(x2 - __half2float(h2)),
                            __float2half_rn(x3 - __half2float(h3)));
        unsigned* base = S + row * 16;
        *reinterpret_cast<uint2*>(base + (p0 & 3) * 4 + ((p0 >> 2) << 1)) = make_uint2(H0, L0);
        *reinterpret_cast<uint2*>(base + (p1 & 3) * 4 + ((p1 >> 2) << 1)) = make_uint2(H1, L1);
    } else {
        unsigned* base = S + row * 8;
        base[(p0 & 3) * 2 + (p0 >> 2)] = H0;
        base[(p1 & 3) * 2 + (p1 >> 2)] = H1;
    }
}

// ---------------- tensor-core NT GEMM: C = act(A) @ W^T (+ fused epilogues) ---------
// A: [M,K] rm, W: [N,K] rm. Tile 128x128, k-chunk 16, 8 warps, warptile 64x32.
// Double-buffered smem, 1 sync per chunk.
// SPLIT=true: 3x fp16 error-compensated (~2^-21). SPLIT=false: plain fp16 (~2^-11).
// AACT: 0 none, 1 silu(A). EPI: 0 C=acc | 1 C+=acc | 2 C+=acc*E | 3 C=silu(acc)*E
template<bool SPLIT, int AACT, int EPI>
__global__ void __launch_bounds__(256) gemm_tc(
    const float* __restrict__ A, const float* __restrict__ W,
    float* __restrict__ C, const float* __restrict__ E,
    int M, int N, int K)
{
    constexpr int RSU = SPLIT ? 16 : 8;     // u32 per row
    __shared__ unsigned As[2 * 128 * RSU];
    __shared__ unsigned Bs[2 * 128 * RSU];

    const int tid  = threadIdx.x;
    const int lane = tid & 31;
    const int gr   = lane >> 2;     // 0..7
    const int tc   = lane & 3;      // 0..3
    const int warp = tid >> 5;
    const int wm   = warp >> 2;     // 0..1
    const int wn   = warp & 3;      // 0..3
    const long bm = (long)blockIdx.y * 128;
    const long bn = (long)blockIdx.x * 128;

    const int r0 = tid >> 2;        // staging row (0..63), second batch +64
    const int i4 = tid & 3;

    const float* Ag = A + (bm + r0) * (long)K + i4 * 4;
    const float* Bg = W + (bn + r0) * (long)K + i4 * 4;
    const long halfA = 64 * (long)K;

    float acc[4][4][4];
    #pragma unroll
    for (int mi = 0; mi < 4; mi++)
        #pragma unroll
        for (int ni = 0; ni < 4; ni++)
            #pragma unroll
            for (int r = 0; r < 4; r++) acc[mi][ni][r] = 0.0f;

    float4 ra0 = *reinterpret_cast<const float4*>(Ag);
    float4 ra1 = *reinterpret_cast<const float4*>(Ag + halfA);
    float4 rb0 = *reinterpret_cast<const float4*>(Bg);
    float4 rb1 = *reinterpret_cast<const float4*>(Bg + halfA);

    stage_row<SPLIT, AACT>(As, r0,      i4, ra0);
    stage_row<SPLIT, AACT>(As, r0 + 64, i4, ra1);
    stage_row<SPLIT, 0   >(Bs, r0,      i4, rb0);
    stage_row<SPLIT, 0   >(Bs, r0 + 64, i4, rb1);
    __syncthreads();

    const int nIter = K >> 4;
    for (int it = 0; it < nIter; it++) {
        const unsigned* Ab = As + (it & 1) * 128 * RSU;
        const unsigned* Bb = Bs + (it & 1) * 128 * RSU;

        if (it + 1 < nIter) {
            int k1 = (it + 1) << 4;
            ra0 = *reinterpret_cast<const float4*>(Ag + k1);
            ra1 = *reinterpret_cast<const float4*>(Ag + halfA + k1);
            rb0 = *reinterpret_cast<const float4*>(Bg + k1);
            rb1 = *reinterpret_cast<const float4*>(Bg + halfA + k1);
        }

        if (SPLIT) {
            unsigned bhi[4][2], blo[4][2];
            #pragma unroll
            for (int ni = 0; ni < 4; ni++) {
                uint4 f = *reinterpret_cast<const uint4*>(
                    Bb + (wn * 32 + ni * 8 + gr) * 16 + tc * 4);
                bhi[ni][0] = f.x; blo[ni][0] = f.y;
                bhi[ni][1] = f.z; blo[ni][1] = f.w;
            }
            #pragma unroll
            for (int mi = 0; mi < 4; mi++) {
                int r = wm * 64 + mi * 16 + gr;
                uint4 f0 = *reinterpret_cast<const uint4*>(Ab + r * 16 + tc * 4);
                uint4 f1 = *reinterpret_cast<const uint4*>(Ab + (r + 8) * 16 + tc * 4);
                unsigned ahi[4] = {f0.x, f1.x, f0.z, f1.z};
                unsigned alo[4] = {f0.y, f1.y, f0.w, f1.w};
                #pragma unroll
                for (int ni = 0; ni < 4; ni++) {
                    mma_f16(acc[mi][ni], ahi, bhi[ni]);
                    mma_f16(acc[mi][ni], alo, bhi[ni]);
                    mma_f16(acc[mi][ni], ahi, blo[ni]);
                }
            }
        } else {
            unsigned bf[4][2];
            #pragma unroll
            for (int ni = 0; ni < 4; ni++) {
                uint2 f = *reinterpret_cast<const uint2*>(
                    Bb + (wn * 32 + ni * 8 + gr) * 8 + tc * 2);
                bf[ni][0] = f.x; bf[ni][1] = f.y;
            }
            #pragma unroll
            for (int mi = 0; mi < 4; mi++) {
                int r = wm * 64 + mi * 16 + gr;
                uint2 f0 = *reinterpret_cast<const uint2*>(Ab + r * 8 + tc * 2);
                uint2 f1 = *reinterpret_cast<const uint2*>(Ab + (r + 8) * 8 + tc * 2);
                unsigned af[4] = {f0.x, f1.x, f0.y, f1.y};
                #pragma unroll
                for (int ni = 0; ni < 4; ni++)
                    mma_f16(acc[mi][ni], af, bf[ni]);
            }
        }

        if (it + 1 < nIter) {
            unsigned* An = As + ((it + 1) & 1) * 128 * RSU;
            unsigned* Bn = Bs + ((it + 1) & 1) * 128 * RSU;
            stage_row<SPLIT, AACT>(An, r0,      i4, ra0);
            stage_row<SPLIT, AACT>(An, r0 + 64, i4, ra1);
            stage_row<SPLIT, 0   >(Bn, r0,      i4, rb0);
            stage_row<SPLIT, 0   >(Bn, r0 + 64, i4, rb1);
            __syncthreads();
        }
    }

    // epilogue
    #pragma unroll
    for (int mi = 0; mi < 4; mi++) {
        #pragma unroll
        for (int ni = 0; ni < 4; ni++) {
            long row = bm + wm * 64 + mi * 16 + gr;
            long col = bn + wn * 32 + ni * 8 + tc * 2;
            float* a = acc[mi][ni];
            long i0 = row * (long)N + col;
            long i1 = (row + 8) * (long)N + col;
            float2 o0, o1;
            if (EPI == 0) {
                o0 = make_float2(a[0], a[1]);
                o1 = make_float2(a[2], a[3]);
            } else if (EPI == 1) {
                float2 c0 = *reinterpret_cast<float2*>(&C[i0]);
                float2 c1 = *reinterpret_cast<float2*>(&C[i1]);
                o0 = make_float2(c0.x + a[0], c0.y + a[1]);
                o1 = make_float2(c1.x + a[2], c1.y + a[3]);
            } else if (EPI == 2) {
                float2 c0 = *reinterpret_cast<float2*>(&C[i0]);
                float2 c1 = *reinterpret_cast<float2*>(&C[i1]);
                float2 e0 = *reinterpret_cast<const float2*>(&E[i0]);
                float2 e1 = *reinterpret_cast<const float2*>(&E[i1]);
                o0 = make_float2(c0.x + a[0]*e0.x, c0.y + a[1]*e0.y);
                o1 = make_float2(c1.x + a[2]*e1.x, c1.y + a[3]*e1.y);
            } else {
                float2 e0 = *reinterpret_cast<const float2*>(&E[i0]);
                float2 e1 = *reinterpret_cast<const float2*>(&E[i1]);
                o0 = make_float2(silu_f(a[0])*e0.x, silu_f(a[1])*e0.y);
                o1 = make_float2(silu_f(a[2])*e1.x, silu_f(a[3])*e1.y);
            }
            *reinterpret_cast<float2*>(&C[i0]) = o0;
            *reinterpret_cast<float2*>(&C[i1]) = o1;
        }
    }
}

// ---------------- decay attention with band pruning -------------------------------
// out[b,i,:] = sum_{j<=i} exp(nl[b,j]*(i-j)) q[b,j,:]
__global__ void __launch_bounds__(256) decay_attn(
    const float* __restrict__ Q, const float* __restrict__ NLv,
    const float* __restrict__ NM, float* __restrict__ O)
{
    const int it = blockIdx.x;
    const int dt = blockIdx.y;
    const int b  = blockIdx.z;
    const float* q  = Q + (long)b*SS*DIM + dt*64;
    const float* nl = NLv + (long)b*SS;
    const float* nlmax = NM + b*(SS/64);
    __shared__ float qs[64][64];
    __shared__ float nls[64];
    __shared__ float sgs[64];
    const int tid = threadIdx.x;
    const int tx = tid & 15, ty = tid >> 4;
    float acc[4][4] = {};
    const int i0 = it*64 + ty*4;

    for (int jt = 0; jt <= it; jt++) {
        if (jt < it) {
            float dmin = (float)(it*64 - (jt*64 + 63));
            if (nlmax[jt] * dmin < -40.0f) continue;
        }
        {
            int r = tid >> 4;
            int c = (tid & 15) * 4;
            #pragma unroll
            for (int rr = 0; rr < 64; rr += 16) {
                float4 v = *reinterpret_cast<const float4*>(
                    q + (long)(jt*64 + r + rr) * DIM + c);
                *reinterpret_cast<float4*>(&qs[r + rr][c]) = v;
            }
        }
        if (tid < 64) {
            float xv = nl[jt*64 + tid];
            nls[tid] = xv;
            sgs[tid] = expf(xv);
        }
        __syncthreads();

        if (jt < it) {
            #pragma unroll 2
            for (int j = 0; j < 64; j++) {
                float s = sgs[j];
                float w = expf(nls[j] * (float)(i0 - (jt*64 + j)));
                float4 qv = *reinterpret_cast<const float4*>(&qs[j][tx*4]);
                #pragma unroll
                for (int ii = 0; ii < 4; ii++) {
                    acc[ii][0] += w * qv.x;
                    acc[ii][1] += w * qv.y;
                    acc[ii][2] += w * qv.z;
                    acc[ii][3] += w * qv.w;
                    w *= s;
                }
            }
        } else {
            for (int j = 0; j < 64; j++) {
                int jg = jt*64 + j;
                float4 qv = *reinterpret_cast<const float4*>(&qs[j][tx*4]);
                #pragma unroll
                for (int ii = 0; ii < 4; ii++) {
                    int d = i0 + ii - jg;
                    float w = (d >= 0) ? expf(nls[j] * (float)d) : 0.0f;
                    acc[ii][0] += w * qv.x;
                    acc[ii][1] += w * qv.y;
                    acc[ii][2] += w * qv.z;
                    acc[ii][3] += w * qv.w;
                }
            }
        }
        __syncthreads();
    }

    float* o = O + (long)b*SS*DIM + dt*64;
    #pragma unroll
    for (int ii = 0; ii < 4; ii++) {
        float4 v = {acc[ii][0], acc[ii][1], acc[ii][2], acc[ii][3]};
        *reinterpret_cast<float4*>(o + (long)(i0 + ii) * DIM + tx*4) = v;
    }
}

// ---------------- orchestration ----------------
extern "C" void kernel_launch(void* const* d_in, const int* in_sizes, int n_in,
                              void* d_out, int out_size) {
    const int*   tokens       = (const int*)  d_in[0];
    const float* emb          = (const float*)d_in[1];
    const float* decay_norm_w = (const float*)d_in[2];
    const float* lambda_w     = (const float*)d_in[3];
    const float* quantity_w   = (const float*)d_in[4];
    const float* gate_w       = (const float*)d_in[5];
    const float* output_w     = (const float*)d_in[6];
    const float* ffn_norm_w   = (const float*)d_in[7];
    const float* w_h          = (const float*)d_in[8];
    const float* w_g          = (const float*)d_in[9];
    const float* w_o          = (const float*)d_in[10];
    const float* out_norm_w   = (const float*)d_in[11];
    float* out = (float*)d_out;

    float *x, *h, *q, *g, *ao, *f, *a, *t, *nl, *nm;
    cudaGetSymbolAddress((void**)&x,  g_x);
    cudaGetSymbolAddress((void**)&h,  g_h);
    cudaGetSymbolAddress((void**)&q,  g_q);
    cudaGetSymbolAddress((void**)&g,  g_g);
    cudaGetSymbolAddress((void**)&ao, g_ao);
    cudaGetSymbolAddress((void**)&f,  g_f);
    cudaGetSymbolAddress((void**)&a,  g_a);
    cudaGetSymbolAddress((void**)&t,  g_t);
    cudaGetSymbolAddress((void**)&nl, g_nl);
    cudaGetSymbolAddress((void**)&nm, g_nlmax);

    embed_kernel<<<M_TOT * (DIM/4) / 256, 256>>>(tokens, emb, x);

    dim3 g512 (DIM/128,   M_TOT/128);   // (4,  32)
    dim3 g2048(HID/128,   M_TOT/128);   // (16, 32)
    dim3 gV   (VOCAB/128, M_TOT/128);   // (250,32)
    dim3 gattn(SS/64, DIM/64, BB);      // (32, 8, 2)

    for (int l = 0; l < NLAYERS; l++) {
        rmsnorm_kernel<true><<<M_TOT, 128>>>(x, decay_norm_w + l*DIM,
                                             lambda_w + l*DIM, h, nl);
        nlmax_kernel<<<M_TOT/64, 32>>>(nl, nm);
        gemm_tc<true,0,0><<<g512, 256>>>(h, quantity_w + (long)l*DIM*DIM, q, nullptr,
                                         M_TOT, DIM, DIM);
        gemm_tc<true,0,0><<<g512, 256>>>(h, gate_w + (long)l*DIM*DIM, g, nullptr,
                                         M_TOT, DIM, DIM);
        decay_attn<<<gattn, 256>>>(q, nl, nm, ao);
        gemm_tc<true,1,2><<<g512, 256>>>(ao, output_w + (long)l*DIM*DIM, x, g,
                                         M_TOT, DIM, DIM);
        rmsnorm_kernel<false><<<M_TOT, 128>>>(x, ffn_norm_w + l*DIM,
                                              nullptr, f, nullptr);
        gemm_tc<true,0,0><<<g2048, 256>>>(f, w_h + (long)l*HID*DIM, a, nullptr,
                                          M_TOT, HID, DIM);
        gemm_tc<true,0,3><<<g2048, 256>>>(f, w_g + (long)l*HID*DIM, t, a,
                                          M_TOT, HID, DIM);
        gemm_tc<true,0,1><<<g512, 256>>>(t, w_o + (long)l*DIM*HID, x, nullptr,
                                         M_TOT, DIM, HID);
    }

    rmsnorm_kernel<false><<<M_TOT, 128>>>(x, out_norm_w, nullptr, h, nullptr);
    gemm_tc<false,0,0><<<gV, 256>>>(h, emb, out, nullptr, M_TOT, VOCAB, DIM);
}